// round 11
// baseline (speedup 1.0000x reference)
#include <cuda_runtime.h>
#include <cuda_fp16.h>
#include <stdint.h>

// Problem constants
#define kB 128
#define kT 2048
#define kI 128
#define kH 256
#define kO 128

#define LDW  392   // LSTM B stride (K=384 padded)
#define LDH  264   // h buffers stride (K=256 padded; uint4-safe)
#define LDX  136   // x buffer stride (K=128 padded; uint4-safe)

// Persistent device state (zero-initialized at module load)
__device__ __half g_h1[2][2][kB][kH];   // [dir][parity][b][h]
__device__ __half g_h2[2][2][kB][kH];
__device__ float  g_hf[2][kB][kH];      // final h2 fp32
__device__ unsigned g_flag[8][32 * 32]; // [group][ng*32]: 128B stride per flag
__device__ unsigned g_cnt[4];
__device__ unsigned g_epoch[4];

struct __align__(16) SM {
    __half wL[64][LDW];     // LSTM weights u-major: row = u*4+gate; cols [0,128)=w1x, [128,384)=w1h
    __half w2x[64][LDH];    // GRU x-weights u-major padded: row = u*4+gate (gate 3 = zeros)
    __half w2h[64][LDH];    // GRU h-weights u-major padded
    __half xbuf[2][32][LDX];// double-buffered x_t (fp16)
    __half aH[32][LDH];     // staged h1(k)
    __half a2[32][LDH];     // staged h2(k-1)
    float bL[64];           // u-major: [u*4+gate] = b1x+b1h
    float b2xp[64];         // u-major padded
    float b2hp[64];
};

__device__ __forceinline__ float sigf(float x) {
    return __fdividef(1.0f, 1.0f + __expf(-x));
}
__device__ __forceinline__ float tanhfast(float x) {
    return 2.0f * sigf(2.0f * x) - 1.0f;
}

__device__ __forceinline__ unsigned ld_acq(const unsigned* p) {
    unsigned v;
    asm volatile("ld.acquire.gpu.u32 %0, [%1];" : "=r"(v) : "l"(p) : "memory");
    return v;
}
__device__ __forceinline__ void st_rel(unsigned* p, unsigned v) {
    asm volatile("st.release.gpu.u32 [%0], %1;" :: "l"(p), "r"(v) : "memory");
}
__device__ __forceinline__ void barn(int id, int cnt) {
    asm volatile("bar.sync %0, %1;" :: "r"(id), "r"(cnt) : "memory");
}

// All-CTA sense-reversal barrier (used once before the FC)
__device__ __forceinline__ void gbar_all(int slot, unsigned target) {
    __syncthreads();
    if (threadIdx.x == 0) {
        __threadfence();
        unsigned e = ld_acq(&g_epoch[slot]);
        unsigned old = atomicAdd(&g_cnt[slot], 1u);
        if (old == target - 1u) {
            g_cnt[slot] = 0u;
            __threadfence();
            atomicAdd(&g_epoch[slot], 1u);
        } else {
            while (ld_acq(&g_epoch[slot]) == e) { }
        }
    }
    __syncthreads();
}

// ldmatrix / mma helpers
__device__ __forceinline__ unsigned sptr(const void* p) {
    return (unsigned)__cvta_generic_to_shared(p);
}
__device__ __forceinline__ void lda16x16(unsigned* r, const __half* base, int lda) {
    int lane = threadIdx.x & 31;
    const __half* p = base + (lane & 15) * lda + (lane >> 4) * 8;
    unsigned a = sptr(p);
    asm volatile("ldmatrix.sync.aligned.m8n8.x4.shared.b16 {%0,%1,%2,%3},[%4];"
                 : "=r"(r[0]), "=r"(r[1]), "=r"(r[2]), "=r"(r[3]) : "r"(a));
}
__device__ __forceinline__ void ldb16x8(unsigned* r, const __half* base, int ldb) {
    int lane = threadIdx.x & 31;
    int l = lane & 15;
    const __half* p = base + (l & 7) * ldb + (l >> 3) * 8;
    unsigned a = sptr(p);
    asm volatile("ldmatrix.sync.aligned.m8n8.x2.shared.b16 {%0,%1},[%2];"
                 : "=r"(r[0]), "=r"(r[1]) : "r"(a));
}
__device__ __forceinline__ void mma16816(float* c, const unsigned* a, const unsigned* b) {
    asm volatile("mma.sync.aligned.m16n8k16.row.col.f32.f16.f16.f32 "
                 "{%0,%1,%2,%3},{%4,%5,%6,%7},{%8,%9},{%0,%1,%2,%3};"
                 : "+f"(c[0]), "+f"(c[1]), "+f"(c[2]), "+f"(c[3])
                 : "r"(a[0]), "r"(a[1]), "r"(a[2]), "r"(a[3]), "r"(b[0]), "r"(b[1]));
}

// x staging: 128 threads (tl in [0,128)), 1024 float4s, batched.
__device__ __forceinline__ void stage_x128(SM& s, const float* __restrict__ x,
                                           int buf, int t, int row0, int tl) {
    float4 f[8];
    #pragma unroll
    for (int q = 0; q < 8; q++) {
        int idx = tl + 128 * q;
        f[q] = __ldg((const float4*)(x + ((size_t)(row0 + (idx >> 5)) * kT + t) * kI)
                     + (idx & 31));
    }
    #pragma unroll
    for (int q = 0; q < 8; q++) {
        int idx = tl + 128 * q;
        __half2* dst = (__half2*)&s.xbuf[buf][idx >> 5][(idx & 31) * 4];
        dst[0] = __floats2half2_rn(f[q].x, f[q].y);
        dst[1] = __floats2half2_rn(f[q].z, f[q].w);
    }
}

__global__ void __launch_bounds__(512, 1) brnn_kernel(
    const float* __restrict__ x,
    const float* __restrict__ w1x, const float* __restrict__ b1x,
    const float* __restrict__ w1h, const float* __restrict__ b1h,
    const float* __restrict__ w2x, const float* __restrict__ b2x,
    const float* __restrict__ w2h, const float* __restrict__ b2h,
    const float* __restrict__ wo,  const float* __restrict__ bo,
    float* __restrict__ out)
{
    extern __shared__ __align__(16) char smraw[];
    SM& s = *reinterpret_cast<SM*>(smraw);
    const int tid = threadIdx.x;
    const int lane = tid & 31;
    const int d = blockIdx.x >> 6;       // direction
    const int g = blockIdx.x & 63;
    const int bg = g & 3, ng = g >> 2;   // batch-group (32 rows), hidden-group (16 units)
    const int row0 = bg * 32, hu0 = ng * 16;
    const int grp = d * 4 + bg;          // 16-CTA communication group
    const int w = tid >> 5;

    // ---- load weight slices to SMEM, u-major permuted (fp16) ----
    for (int idx = tid; idx < 64 * 384; idx += 512) {
        int r = idx / 384, cc = idx - r * 384;
        int u = r >> 2, gg = r & 3;
        int gr = gg * kH + hu0 + u;
        float v = (cc < kI) ? w1x[gr * kI + cc] : w1h[gr * kH + (cc - kI)];
        s.wL[r][cc] = __float2half_rn(v);
    }
    for (int idx = tid; idx < 64 * 256; idx += 512) {
        int r = idx >> 8, cc = idx & 255;
        int u = r >> 2, gg = r & 3;
        float vx = 0.f, vh = 0.f;
        if (gg < 3) {
            int gr = gg * kH + hu0 + u;
            vx = w2x[gr * kH + cc];
            vh = w2h[gr * kH + cc];
        }
        s.w2x[r][cc] = __float2half_rn(vx);
        s.w2h[r][cc] = __float2half_rn(vh);
    }
    if (tid < 64) {
        int u = tid >> 2, gg = tid & 3;
        int gr = gg * kH + hu0 + u;
        s.bL[tid] = b1x[gr] + b1h[gr];
        s.b2xp[tid] = (gg < 3) ? b2x[gg * kH + hu0 + u] : 0.f;
        s.b2hp[tid] = (gg < 3) ? b2h[gg * kH + hu0 + u] : 0.f;
    }
    // zero my slice of parity-0 global state (512 units, 1/thread)
    {
        int b = tid >> 4, u = tid & 15;
        g_h1[d][0][row0 + b][hu0 + u] = __float2half_rn(0.f);
        g_h2[d][0][row0 + b][hu0 + u] = __float2half_rn(0.f);
    }
    __threadfence();
    __syncthreads();

    // ---- preload static B fragments + biases into registers ----
    unsigned bfa[16][2], bfb[16][2];   // LSTM: sf0/sf1 h-part; GRU: x/h mats
    float biasa[8];                    // LSTM: blr[2][4]; GRU: bx[3],bh[3]
    float st0 = 0.f, st1 = 0.f, st2 = 0.f, st3 = 0.f;  // c1 (LSTM: 4) / h2 (GRU: 2)
    if (w < 4) {
        #pragma unroll
        for (int kk = 0; kk < 16; kk++) {
            ldb16x8(bfa[kk], &s.wL[16 * w][128 + kk * 16], LDW);        // sf 0
            ldb16x8(bfb[kk], &s.wL[16 * w + 8][128 + kk * 16], LDW);    // sf 1
        }
        #pragma unroll
        for (int sf = 0; sf < 2; sf++) {
            int ul = 4 * w + sf * 2 + ((lane & 3) >> 1);
            #pragma unroll
            for (int gg = 0; gg < 4; gg++)
                biasa[sf * 4 + gg] = s.bL[ul * 4 + gg];
        }
    } else if (w < 12) {
        const int j = w - 4;
        #pragma unroll
        for (int kk = 0; kk < 16; kk++) {
            ldb16x8(bfa[kk], &s.w2x[8 * j][kk * 16], LDH);
            ldb16x8(bfb[kk], &s.w2h[8 * j][kk * 16], LDH);
        }
        int ul = 2 * j + ((lane & 3) >> 1);
        #pragma unroll
        for (int gg = 0; gg < 3; gg++) {
            biasa[gg]     = s.b2xp[ul * 4 + gg];
            biasa[4 + gg] = s.b2hp[ul * 4 + gg];
        }
    }
    // publish zero-init flag; stage x(0) with stage warps 12-15
    if (tid == 0) st_rel(&g_flag[grp][ng * 32], 1u);
    if (w >= 12)
        stage_x128(s, x, 0, d ? (kT - 1) : 0, row0, tid - 384);
    __syncthreads();

    const bool oddl = (lane & 1) != 0;
    const int rbase = (lane >> 2) + (oddl ? 8 : 0);

    // ---- main recurrence: iteration k computes h1(k+1) and h2(k) ----
    for (int k = 0; k <= kT; k++) {
        const int par = k & 1;
        const int xb = k & 1;

        if (w < 4) {
            // ============ LSTM warp: x-GEMM before sync, h-GEMM + eltwise after ====
            float acc[2][2][4] = {};
            if (k < kT) {
                #pragma unroll
                for (int m = 0; m < 2; m++) {
                    #pragma unroll
                    for (int kk = 0; kk < 8; kk++) {
                        unsigned a[4];
                        lda16x16(a, &s.xbuf[xb][m * 16][kk * 16], LDX);
                        #pragma unroll
                        for (int sf = 0; sf < 2; sf++) {
                            unsigned b[2];
                            ldb16x8(b, &s.wL[16 * w + sf * 8][kk * 16], LDW);
                            mma16816(acc[m][sf], a, b);
                        }
                    }
                }
            }
            __syncthreads();   // sync1
            if (k < kT) {
                #pragma unroll
                for (int m = 0; m < 2; m++) {
                    #pragma unroll
                    for (int kk = 0; kk < 16; kk++) {
                        unsigned a[4];
                        lda16x16(a, &s.aH[m * 16][kk * 16], LDH);
                        mma16816(acc[m][0], a, bfa[kk]);
                        mma16816(acc[m][1], a, bfb[kk]);
                    }
                }
                // in-register eltwise: shfl gate exchange, even=row r / odd=row r+8
                float* cst[4] = {&st0, &st1, &st2, &st3};
                #pragma unroll
                for (int m = 0; m < 2; m++) {
                    #pragma unroll
                    for (int sf = 0; sf < 2; sf++) {
                        float o0 = acc[m][sf][0], o1 = acc[m][sf][1];
                        float o2 = acc[m][sf][2], o3 = acc[m][sf][3];
                        float p0 = __shfl_xor_sync(0xffffffffu, o0, 1);
                        float p1 = __shfl_xor_sync(0xffffffffu, o1, 1);
                        float p2 = __shfl_xor_sync(0xffffffffu, o2, 1);
                        float p3 = __shfl_xor_sync(0xffffffffu, o3, 1);
                        float iv = (oddl ? p2 : o0) + biasa[sf * 4 + 0];
                        float fv = (oddl ? p3 : o1) + biasa[sf * 4 + 1];
                        float gv = (oddl ? o2 : p0) + biasa[sf * 4 + 2];
                        float ov = (oddl ? o3 : p1) + biasa[sf * 4 + 3];
                        float cn = (*cst[m * 2 + sf]) * sigf(fv) + sigf(iv) * tanhfast(gv);
                        *cst[m * 2 + sf] = cn;
                        float h1 = sigf(ov) * tanhfast(cn);
                        int b = m * 16 + rbase;
                        int ul = 4 * w + sf * 2 + ((lane & 3) >> 1);
                        g_h1[d][par ^ 1][row0 + b][hu0 + ul] = __float2half_rn(h1);
                    }
                }
            }
        } else if (w < 12) {
            // ============ GRU warp: both GEMMs + eltwise after sync ================
            const int j = w - 4;
            float ax[2][4] = {}, ah[2][4] = {};
            __syncthreads();   // sync1
            #pragma unroll
            for (int m = 0; m < 2; m++) {
                #pragma unroll
                for (int kk = 0; kk < 16; kk++) {
                    unsigned a[4];
                    lda16x16(a, &s.aH[m * 16][kk * 16], LDH);
                    mma16816(ax[m], a, bfa[kk]);
                }
            }
            #pragma unroll
            for (int m = 0; m < 2; m++) {
                #pragma unroll
                for (int kk = 0; kk < 16; kk++) {
                    unsigned a[4];
                    lda16x16(a, &s.a2[m * 16][kk * 16], LDH);
                    mma16816(ah[m], a, bfb[kk]);
                }
            }
            float* hst[2] = {&st0, &st1};
            #pragma unroll
            for (int m = 0; m < 2; m++) {
                float px0 = __shfl_xor_sync(0xffffffffu, ax[m][0], 1);
                float px1 = __shfl_xor_sync(0xffffffffu, ax[m][1], 1);
                float px2 = __shfl_xor_sync(0xffffffffu, ax[m][2], 1);
                float px3 = __shfl_xor_sync(0xffffffffu, ax[m][3], 1);
                float ph0 = __shfl_xor_sync(0xffffffffu, ah[m][0], 1);
                float ph1 = __shfl_xor_sync(0xffffffffu, ah[m][1], 1);
                float ph2 = __shfl_xor_sync(0xffffffffu, ah[m][2], 1);
                float ph3 = __shfl_xor_sync(0xffffffffu, ah[m][3], 1);
                float xr = oddl ? px2 : ax[m][0];
                float xz = oddl ? px3 : ax[m][1];
                float xn = oddl ? ax[m][2] : px0;
                float hr = oddl ? ph2 : ah[m][0];
                float hz = oddl ? ph3 : ah[m][1];
                float hn = oddl ? ah[m][2] : ph0;
                float rr = sigf(xr + biasa[0] + hr + biasa[4]);
                float zz = sigf(xz + biasa[1] + hz + biasa[5]);
                float nn = tanhfast(xn + biasa[2] + rr * (hn + biasa[6]));
                float h2 = zz * (*hst[m]) + (1.f - zz) * nn;
                *hst[m] = h2;
                int b = m * 16 + rbase;
                int ul = 2 * j + ((lane & 3) >> 1);
                g_h2[d][par ^ 1][row0 + b][hu0 + ul] = __float2half_rn(h2);
                if (k == kT) g_hf[d][row0 + b][hu0 + ul] = h2;
            }
        } else {
            // ============ stage warps 12-15: poll, stage h, prefetch x =============
            const int tl = tid - 384;
            if (w == 12 && lane < 16) {
                const unsigned* fp = &g_flag[grp][lane * 32];
                const unsigned ep = (unsigned)(k + 1);
                while (ld_acq(fp) < ep) { }
            }
            barn(1, 128);
            {
                const uint4* s1 = (const uint4*)&g_h1[d][par][row0][0];
                const uint4* s2 = (const uint4*)&g_h2[d][par][row0][0];
                uint4 v1[8], v2[8];
                #pragma unroll
                for (int q = 0; q < 8; q++) v1[q] = __ldcg(s1 + tl + 128 * q);
                #pragma unroll
                for (int q = 0; q < 8; q++) v2[q] = __ldcg(s2 + tl + 128 * q);
                #pragma unroll
                for (int q = 0; q < 8; q++) {
                    int idx = tl + 128 * q;
                    *((uint4*)&s.aH[idx >> 5][0] + (idx & 31)) = v1[q];
                }
                #pragma unroll
                for (int q = 0; q < 8; q++) {
                    int idx = tl + 128 * q;
                    *((uint4*)&s.a2[idx >> 5][0] + (idx & 31)) = v2[q];
                }
            }
            __syncthreads();   // sync1
            if (k + 1 < kT) {
                const int t = d ? (kT - 2 - k) : (k + 1);
                stage_x128(s, x, xb ^ 1, t, row0, tl);
            }
        }

        if (k == kT) break;

        // publish this step's state
        __threadfence();
        __syncthreads();       // sync2
        if (tid == 0) st_rel(&g_flag[grp][ng * 32], (unsigned)(k + 2));
    }

    // ---- all-CTA barrier, reset flags for next graph replay ----
    __threadfence();
    gbar_all(2, 128);
    if (tid == 0) g_flag[grp][ng * 32] = 0;

    // ---- final FC: out = [h_fwd | h_bwd] @ wo^T + bo ----
    if (blockIdx.x < 16) {
        float* sh = (float*)&s;              // reuse SMEM: [8][512]
        int b0r = blockIdx.x * 8;
        for (int idx = tid; idx < 8 * 512; idx += 512) {
            int br = idx >> 9, jj = idx & 511;
            sh[idx] = (jj < 256) ? __ldcg(&g_hf[0][b0r + br][jj])
                                 : __ldcg(&g_hf[1][b0r + br][jj - 256]);
        }
        __syncthreads();
        for (int it = tid; it < 8 * 128; it += 512) {
            int br = it >> 7, o = it & 127;
            float acc = bo[o];
            const float* wrow = wo + o * 512;
            const float* hrow = sh + br * 512;
            #pragma unroll 8
            for (int jj = 0; jj < 512; jj++) acc += hrow[jj] * wrow[jj];
            out[(size_t)(b0r + br) * kO + o] = acc;
        }
    }
}

extern "C" void kernel_launch(void* const* d_in, const int* in_sizes, int n_in,
                              void* d_out, int out_size)
{
    const float* x   = (const float*)d_in[0];
    const float* w1x = (const float*)d_in[1];
    const float* b1x = (const float*)d_in[2];
    const float* w1h = (const float*)d_in[3];
    const float* b1h = (const float*)d_in[4];
    const float* w2x = (const float*)d_in[5];
    const float* b2x = (const float*)d_in[6];
    const float* w2h = (const float*)d_in[7];
    const float* b2h = (const float*)d_in[8];
    const float* wo  = (const float*)d_in[9];
    const float* bo  = (const float*)d_in[10];

    cudaFuncSetAttribute(brnn_kernel, cudaFuncAttributeMaxDynamicSharedMemorySize,
                         (int)sizeof(SM));
    brnn_kernel<<<128, 512, sizeof(SM)>>>(x, w1x, b1x, w1h, b1h,
                                          w2x, b2x, w2h, b2h, wo, bo,
                                          (float*)d_out);
}